// round 14
// baseline (speedup 1.0000x reference)
#include <cuda_runtime.h>

#define N_NODES 50000
#define MAX_E   900000

// Scratch (device globals — no allocation allowed)
__device__ float g_h0[N_NODES * 128];
__device__ float g_h [N_NODES * 128];
__device__ float g_h2[N_NODES * 64];
__device__ int   g_cnt_in[N_NODES];
__device__ int   g_cnt_out[N_NODES];
__device__ int   g_off_in[N_NODES];
__device__ int   g_off_out[N_NODES];
__device__ int   g_cur_in[N_NODES];
__device__ int   g_cur_out[N_NODES];
__device__ int   g_csr_in[MAX_E];
__device__ int   g_csr_out[MAX_E];
__device__ int   g_base_in;
__device__ int   g_base_out;

typedef unsigned long long u64;

__device__ __forceinline__ u64 pack2(float lo, float hi) {
    u64 r; asm("mov.b64 %0, {%1, %2};" : "=l"(r) : "f"(lo), "f"(hi)); return r;
}
__device__ __forceinline__ void unpack2(u64 v, float& lo, float& hi) {
    asm("mov.b64 {%0, %1}, %2;" : "=f"(lo), "=f"(hi) : "l"(v));
}
__device__ __forceinline__ void fma2(u64& acc, u64 a, u64 b) {
    asm("fma.rn.f32x2 %0, %1, %2, %0;" : "+l"(acc) : "l"(a), "l"(b));
}

__global__ void zero_cnt_kernel(int n) {
    int i = blockIdx.x * blockDim.x + threadIdx.x;
    if (i < n) { g_cnt_in[i] = 0; g_cnt_out[i] = 0; }
    if (i == 0) { g_base_in = 0; g_base_out = 0; }
}

// ---- latency-phase worker bodies (4 edges / thread, E % 4 == 0) ----
__device__ __forceinline__ void degree_work(int i, const int* __restrict__ ei, int E) {
    if (i * 4 < E) {
        int4 r = ((const int4*)ei)[i];
        int4 c = ((const int4*)(ei + E))[i];
        atomicAdd(&g_cnt_out[r.x], 1); atomicAdd(&g_cnt_out[r.y], 1);
        atomicAdd(&g_cnt_out[r.z], 1); atomicAdd(&g_cnt_out[r.w], 1);
        atomicAdd(&g_cnt_in[c.x], 1); atomicAdd(&g_cnt_in[c.y], 1);
        atomicAdd(&g_cnt_in[c.z], 1); atomicAdd(&g_cnt_in[c.w], 1);
    }
}
__device__ __forceinline__ void fill_one(int r, int c) {
    int p = atomicAdd(&g_cur_in[c], 1);
    g_csr_in[p] = r;
    int q = atomicAdd(&g_cur_out[r], 1);
    g_csr_out[q] = c;
}
__device__ __forceinline__ void fill_work(int i, const int* __restrict__ ei, int E) {
    if (i * 4 < E) {
        int4 r = ((const int4*)ei)[i];
        int4 c = ((const int4*)(ei + E))[i];
        fill_one(r.x, c.x); fill_one(r.y, c.y);
        fill_one(r.z, c.z); fill_one(r.w, c.w);
    }
}

// fallback (E % 4 != 0)
__global__ void degree_kernel1(const int* __restrict__ ei, int E) {
    int i = blockIdx.x * blockDim.x + threadIdx.x;
    if (i < E) {
        atomicAdd(&g_cnt_out[ei[i]], 1);
        atomicAdd(&g_cnt_in[ei[E + i]], 1);
    }
}
__global__ void fill_kernel1(const int* __restrict__ ei, int E) {
    int e = blockIdx.x * blockDim.x + threadIdx.x;
    if (e < E) fill_one(ei[e], ei[E + e]);
}

// Block-local exclusive scan + atomic block base -> CSR segment starts.
__global__ void offsets_kernel(int n) {
    const int* cnt;
    int *off, *cur, *gbase;
    if (blockIdx.y == 0) { cnt = g_cnt_in;  off = g_off_in;  cur = g_cur_in;  gbase = &g_base_in; }
    else                 { cnt = g_cnt_out; off = g_off_out; cur = g_cur_out; gbase = &g_base_out; }

    __shared__ int wsum[32];
    __shared__ int sbase;
    int tid = threadIdx.x, lane = tid & 31, warp = tid >> 5;
    int v = blockIdx.x * blockDim.x + tid;
    int c = (v < n) ? cnt[v] : 0;
    int val = c;
#pragma unroll
    for (int d = 1; d < 32; d <<= 1) {
        int t = __shfl_up_sync(0xffffffffu, val, d);
        if (lane >= d) val += t;
    }
    if (lane == 31) wsum[warp] = val;
    __syncthreads();
    if (warp == 0) {
        int w = wsum[lane];
#pragma unroll
        for (int d = 1; d < 32; d <<= 1) {
            int t = __shfl_up_sync(0xffffffffu, w, d);
            if (lane >= d) w += t;
        }
        wsum[lane] = w;
    }
    __syncthreads();
    int incl = val + (warp ? wsum[warp - 1] : 0);
    if (tid == blockDim.x - 1) sbase = atomicAdd(gbase, incl);
    __syncthreads();
    if (v < n) {
        int o = sbase + incl - c;
        off[v] = o;
        cur[v] = o;
    }
}

// ---------------------------------------------------------------------------
// f32x2 GEMM body (unchanged from R10's proven version).
// 256 threads = 8 warps; warp = 8 rows; lane = VEC=OUTC/32 adjacent cols.
// ---------------------------------------------------------------------------
template<int OUTC>
__device__ __forceinline__ void gemm_body(int bid,
                                          const float* __restrict__ X,
                                          const float* __restrict__ W,
                                          const float* __restrict__ B,
                                          float* __restrict__ Y,
                                          int n, float* smF) {
    constexpr int INC  = 128;
    constexpr int VEC  = OUTC / 32;
    constexpr int NP   = VEC / 2;
    constexpr int OUTP = OUTC + 4;
    float* Wf = smF;                     // [INC][OUTP]
    float* Xs = smF + INC * OUTP;        // [64][INC]

    int tid = threadIdx.x, lane = tid & 31, warp = tid >> 5;

    for (int i = tid; i < OUTC * INC; i += 256) {
        int j = i / INC, k = i - j * INC;
        Wf[k * OUTP + j] = W[i];
    }

    int rowBase = bid * 64 + warp * 8;
    float* xw = Xs + warp * 8 * INC;
#pragma unroll
    for (int r = 0; r < 8; r++) {
        int row = rowBase + r;
        if (row < n)
            ((float4*)(xw + r * INC))[lane] =
                ((const float4*)(X + (size_t)row * INC))[lane];
    }
    __syncthreads();

    u64 acc[8][NP];
    {
        u64 binit[NP];
#pragma unroll
        for (int p = 0; p < NP; p++)
            binit[p] = pack2(B[lane * VEC + 2 * p], B[lane * VEC + 2 * p + 1]);
#pragma unroll
        for (int r = 0; r < 8; r++)
#pragma unroll
            for (int p = 0; p < NP; p++) acc[r][p] = binit[p];
    }

    const float* wl = Wf + lane * VEC;
#pragma unroll 2
    for (int k0 = 0; k0 < INC; k0 += 4) {
        float4 xv[8];
#pragma unroll
        for (int r = 0; r < 8; r++)
            xv[r] = *(const float4*)(xw + r * INC + k0);
#pragma unroll
        for (int kk = 0; kk < 4; kk++) {
            u64 w0, w1;
            const float* wb = wl + (k0 + kk) * OUTP;
            if constexpr (NP == 2) {
                ulonglong2 wg = *(const ulonglong2*)wb;
                w0 = wg.x; w1 = wg.y;
            } else {
                w0 = *(const u64*)wb; w1 = 0;
            }
#pragma unroll
            for (int r = 0; r < 8; r++) {
                float xs = ((const float*)&xv[r])[kk];
                u64 xx = pack2(xs, xs);
                fma2(acc[r][0], xx, w0);
                if constexpr (NP == 2) fma2(acc[r][1], xx, w1);
            }
        }
    }

#pragma unroll
    for (int r = 0; r < 8; r++) {
        int row = rowBase + r;
        if (row < n) {
            float res[VEC];
#pragma unroll
            for (int p = 0; p < NP; p++)
                unpack2(acc[r][p], res[2 * p], res[2 * p + 1]);
            if constexpr (VEC == 4) {
                float4 o = make_float4(res[0], res[1], res[2], res[3]);
                ((float4*)(Y + (size_t)row * OUTC))[lane] = o;
            } else {
                float2 o = make_float2(res[0], res[1]);
                ((float2*)(Y + (size_t)row * OUTC))[lane] = o;
            }
        }
    }
}

// Fused: G gemm128 blocks (row slab starting at gemmBase*64) interleaved with
// F latency blocks (mode 0 = degree, 1 = fill) at period `stride`, so every
// resident wave carries both FMA-bound and LSU/L2-bound work.
__global__ void fused_gemm_lat(int G, int stride, int gemmBase, int mode,
                               const float* __restrict__ X,
                               const float* __restrict__ W,
                               const float* __restrict__ B,
                               float* __restrict__ Y, int n,
                               const int* __restrict__ ei, int E) {
    extern __shared__ float smF[];
    int bid = blockIdx.x;
    int q = bid / stride;
    if ((bid % stride) == 0 && q < G) {
        gemm_body<128>(gemmBase + q, X, W, B, Y, n, smF);
    } else {
        int ng = (bid + stride - 1) / stride;   // gemm blocks before bid
        if (ng > G) ng = G;
        int oi = bid - ng;
        int i = oi * 256 + threadIdx.x;
        if (mode == 0) degree_work(i, ei, E);
        else           fill_work(i, ei, E);
    }
}

__global__ void gemm128_kernel(const float* __restrict__ X, const float* __restrict__ W,
                               const float* __restrict__ B, float* __restrict__ Y, int n) {
    extern __shared__ float smF[];
    gemm_body<128>(blockIdx.x, X, W, B, Y, n, smF);
}
__global__ void gemm64_kernel(const float* __restrict__ X, const float* __restrict__ W,
                              const float* __restrict__ B, float* __restrict__ Y, int n) {
    extern __shared__ float smF[];
    gemm_body<64>(blockIdx.x, X, W, B, Y, n, smF);
}

// CSR gather-aggregation, fused with normalization (and optional ReLU).
template<int C, bool RELU>
__global__ void agg_kernel(const float* __restrict__ src,
                           const int* __restrict__ off,
                           const int* __restrict__ cnt,
                           const int* __restrict__ csr,
                           float* __restrict__ dst, int n) {
    constexpr int LPE = C / 4;
    constexpr int NPW = 32 / LPE;
    int t = blockIdx.x * blockDim.x + threadIdx.x;
    int warp = t >> 5, lane = t & 31;
    int sub = lane / LPE, li = lane - sub * LPE;
    int v = warp * NPW + sub;
    if (v >= n) return;

    int beg = off[v];
    int deg = cnt[v];
    int end = beg + deg;

    float4 acc = ((const float4*)(src + (size_t)v * C))[li];  // self loop
    int e = beg;
    for (; e + 4 <= end; e += 4) {
        int s0 = csr[e], s1 = csr[e + 1], s2 = csr[e + 2], s3 = csr[e + 3];
        float4 a = ((const float4*)(src + (size_t)s0 * C))[li];
        float4 b = ((const float4*)(src + (size_t)s1 * C))[li];
        float4 c = ((const float4*)(src + (size_t)s2 * C))[li];
        float4 d = ((const float4*)(src + (size_t)s3 * C))[li];
        acc.x += (a.x + b.x) + (c.x + d.x);
        acc.y += (a.y + b.y) + (c.y + d.y);
        acc.z += (a.z + b.z) + (c.z + d.z);
        acc.w += (a.w + b.w) + (c.w + d.w);
    }
    for (; e < end; e++) {
        int s = csr[e];
        float4 a = ((const float4*)(src + (size_t)s * C))[li];
        acc.x += a.x; acc.y += a.y; acc.z += a.z; acc.w += a.w;
    }

    float inv = 1.0f / (float)(deg + 1);
    acc.x *= inv; acc.y *= inv; acc.z *= inv; acc.w *= inv;
    if (RELU) {
        acc.x = fmaxf(acc.x, 0.0f); acc.y = fmaxf(acc.y, 0.0f);
        acc.z = fmaxf(acc.z, 0.0f); acc.w = fmaxf(acc.w, 0.0f);
    }
    ((float4*)(dst + (size_t)v * C))[li] = acc;
}

extern "C" void kernel_launch(void* const* d_in, const int* in_sizes, int n_in,
                              void* d_out, int out_size) {
    const float* x  = (const float*)d_in[0];
    const int*   ei = (const int*)d_in[1];
    const float* W1 = (const float*)d_in[2];
    const float* b1 = (const float*)d_in[3];
    const float* W2 = (const float*)d_in[4];
    const float* b2 = (const float*)d_in[5];
    float* out = (float*)d_out;

    int n = in_sizes[0] / 128;
    int E = in_sizes[1] / 2;

    float *h0, *h, *h2;
    int *cnt_in, *cnt_out, *off_in, *off_out, *csr_in, *csr_out;
    cudaGetSymbolAddress((void**)&h0, g_h0);
    cudaGetSymbolAddress((void**)&h,  g_h);
    cudaGetSymbolAddress((void**)&h2, g_h2);
    cudaGetSymbolAddress((void**)&cnt_in,  g_cnt_in);
    cudaGetSymbolAddress((void**)&cnt_out, g_cnt_out);
    cudaGetSymbolAddress((void**)&off_in,  g_off_in);
    cudaGetSymbolAddress((void**)&off_out, g_off_out);
    cudaGetSymbolAddress((void**)&csr_in,  g_csr_in);
    cudaGetSymbolAddress((void**)&csr_out, g_csr_out);

    int smem1 = (128 * (128 + 4) + 64 * 128) * (int)sizeof(float); // 100352
    int smem2 = (128 * (64 + 4)  + 64 * 128) * (int)sizeof(float); // 67584
    cudaFuncSetAttribute(fused_gemm_lat, cudaFuncAttributeMaxDynamicSharedMemorySize, smem1);
    cudaFuncSetAttribute(gemm128_kernel, cudaFuncAttributeMaxDynamicSharedMemorySize, smem1);
    cudaFuncSetAttribute(gemm64_kernel,  cudaFuncAttributeMaxDynamicSharedMemorySize, smem2);

    int gemmTotal = (n + 63) / 64;

    zero_cnt_kernel<<<(n + 255) / 256, 256>>>(n);

    if ((E & 3) == 0) {
        int latB = (E / 4 + 255) / 256;
        int g1 = gemmTotal / 2, g2 = gemmTotal - g1;

        // [degree || gemm128 rows 0..g1*64)
        {
            int total = g1 + latB;
            int stride = total / g1; if (stride < 1) stride = 1;
            fused_gemm_lat<<<total, 256, smem1>>>(g1, stride, 0, 0,
                                                  x, W1, b1, h0, n, ei, E);
        }
        {
            dim3 grid((n + 1023) / 1024, 2);
            offsets_kernel<<<grid, 1024>>>(n);
        }
        // [fill || gemm128 rows g1*64..n)
        {
            int total = g2 + latB;
            int stride = total / g2; if (stride < 1) stride = 1;
            fused_gemm_lat<<<total, 256, smem1>>>(g2, stride, g1, 1,
                                                  x, W1, b1, h0, n, ei, E);
        }
    } else {
        degree_kernel1<<<(E + 255) / 256, 256>>>(ei, E);
        {
            dim3 grid((n + 1023) / 1024, 2);
            offsets_kernel<<<grid, 1024>>>(n);
        }
        fill_kernel1<<<(E + 255) / 256, 256>>>(ei, E);
        gemm128_kernel<<<gemmTotal, 256, smem1>>>(x, W1, b1, h0, n);
    }

    // ---- h = relu(agg_in(h0) / (in_deg+1)) ----
    {
        long threads = (long)n * 32;           // NPW=1 for C=128
        agg_kernel<128, true><<<(int)((threads + 511) / 512), 512>>>(h0, off_in, cnt_in, csr_in, h, n);
    }

    // ---- Layer 2 (flipped edges) ----
    gemm64_kernel<<<(n + 63) / 64, 256, smem2>>>(h, W2, b2, h2, n);
    {
        long threads = ((long)n + 1) / 2 * 32; // NPW=2 for C=64
        agg_kernel<64, false><<<(int)((threads + 511) / 512), 512>>>(h2, off_out, cnt_out, csr_out, out, n);
    }
}